// round 2
// baseline (speedup 1.0000x reference)
#include <cuda_runtime.h>

// SAKE GNN fully fused, one CTA per graph (B=512, M=32, H=128, L=2).
// R2: balanced CTA-wide edge chunks + cp.async double-buffered weight pipeline.

#define NB 512

// ---- shared memory layout (float offsets) ----
#define S_HG    0
#define S_MI    4096
#define S_MJ    8192
#define S_AGG   12288
#define S_WA    16384   // 64x128 weight half (rows 64..127 of current W)
#define S_WB    24576   // 64x128 weight half (rows 0..63 of current W)
#define S_M1    32768   // 2 x (32x128) edge-tile double buffer
#define S_D2    40960   // 32x32
#define S_EDGE  41984   // 1024 ints
#define S_RMASK 43008   // 32 uints
#define S_ROFF  43040   // 32 ints
#define S_X     43072   // 32x3
#define S_HT    43168   // 32x16
#define S_RED   43680   // 8
#define S_NE    43688   // 1 int
#define SM_FLOATS 43696

__device__ __forceinline__ float silu_f(float v) {
    return __fdividef(v, 1.0f + __expf(-v));
}

__device__ __forceinline__ void cp16(unsigned saddr, const float* g) {
    asm volatile("cp.async.cg.shared.global [%0], [%1], 16;" :: "r"(saddr), "l"(g));
}
#define CP_COMMIT() asm volatile("cp.async.commit_group;")
#define CP_WAIT0()  asm volatile("cp.async.wait_group 0;" ::: "memory")

// stage nf4 float4s from g into s (cooperative, async)
__device__ __forceinline__ void stage_async(const float* __restrict__ g,
                                            float* s, int nf4) {
    unsigned sa = (unsigned)__cvta_generic_to_shared(s);
    for (int v = threadIdx.x; v < nf4; v += 256)
        cp16(sa + v * 16, g + v * 4);
}

// acc[rr][c] += sum_{h<nh} X[(i0+rr)*ldx + hbase+h] * W[h*128 + k0 + c]
__device__ __forceinline__ void gemm_piece(const float* __restrict__ sX, int ldx,
                                           int hbase,
                                           const float* __restrict__ sW, int nh,
                                           int i0, int k0, float acc[4][4]) {
    #pragma unroll 1
    for (int h = 0; h < nh; h += 4) {
        float4 w0 = *(const float4*)&sW[(h + 0) * 128 + k0];
        float4 w1 = *(const float4*)&sW[(h + 1) * 128 + k0];
        float4 w2 = *(const float4*)&sW[(h + 2) * 128 + k0];
        float4 w3 = *(const float4*)&sW[(h + 3) * 128 + k0];
        #pragma unroll
        for (int rr = 0; rr < 4; rr++) {
            float4 a = *(const float4*)&sX[(i0 + rr) * ldx + hbase + h];
            acc[rr][0] = fmaf(a.x, w0.x, acc[rr][0]);
            acc[rr][0] = fmaf(a.y, w1.x, acc[rr][0]);
            acc[rr][0] = fmaf(a.z, w2.x, acc[rr][0]);
            acc[rr][0] = fmaf(a.w, w3.x, acc[rr][0]);
            acc[rr][1] = fmaf(a.x, w0.y, acc[rr][1]);
            acc[rr][1] = fmaf(a.y, w1.y, acc[rr][1]);
            acc[rr][1] = fmaf(a.z, w2.y, acc[rr][1]);
            acc[rr][1] = fmaf(a.w, w3.y, acc[rr][1]);
            acc[rr][2] = fmaf(a.x, w0.z, acc[rr][2]);
            acc[rr][2] = fmaf(a.y, w1.z, acc[rr][2]);
            acc[rr][2] = fmaf(a.z, w2.z, acc[rr][2]);
            acc[rr][2] = fmaf(a.w, w3.z, acc[rr][2]);
            acc[rr][3] = fmaf(a.x, w0.w, acc[rr][3]);
            acc[rr][3] = fmaf(a.y, w1.w, acc[rr][3]);
            acc[rr][3] = fmaf(a.z, w2.w, acc[rr][3]);
            acc[rr][3] = fmaf(a.w, w3.w, acc[rr][3]);
        }
    }
}

// Pipelined 128-h GEMM phase.
// Precondition: s_Wb holds rows 0..63 of gW; all threads synced.
// Postcondition: s_Wb holds rows 0..63 of gNext (if non-null); synced.
template <class Epi>
__device__ __forceinline__ void phase128(const float* __restrict__ sX, int ldx,
                                         const float* __restrict__ gW,
                                         const float* __restrict__ gNext,
                                         float* sWa, float* sWb,
                                         int i0, int k0, float acc[4][4], Epi epi) {
    stage_async(gW + 64 * 128, sWa, 2048);
    CP_COMMIT();
    gemm_piece(sX, ldx, 0, sWb, 64, i0, k0, acc);
    CP_WAIT0();
    __syncthreads();
    if (gNext) { stage_async(gNext, sWb, 2048); CP_COMMIT(); }
    gemm_piece(sX, ldx, 64, sWa, 64, i0, k0, acc);
    epi(acc);
    CP_WAIT0();
    __syncthreads();
}

__global__ void __launch_bounds__(256, 1)
sake_kernel(const float* __restrict__ g_h, const float* __restrict__ g_x,
            const float* __restrict__ W_in, const float* __restrict__ b_in,
            const float* __restrict__ We1, const float* __restrict__ be1,
            const float* __restrict__ We2, const float* __restrict__ be2,
            const float* __restrict__ Wh1, const float* __restrict__ bh1,
            const float* __restrict__ Wh2, const float* __restrict__ bh2,
            const float* __restrict__ W_out, const float* __restrict__ b_out,
            const float* __restrict__ Wn1, const float* __restrict__ bn1,
            const float* __restrict__ Wn2, const float* __restrict__ bn2,
            float* __restrict__ g_out)
{
    extern __shared__ float sm[];
    float*    s_hg  = sm + S_HG;
    float*    s_mi  = sm + S_MI;
    float*    s_mj  = sm + S_MJ;
    float*    s_agg = sm + S_AGG;
    float*    s_Wa  = sm + S_WA;
    float*    s_Wb  = sm + S_WB;
    float*    s_m1  = sm + S_M1;
    float*    s_d2  = sm + S_D2;
    int*      s_edge  = (int*)(sm + S_EDGE);
    unsigned* s_rmask = (unsigned*)(sm + S_RMASK);
    int*      s_roff  = (int*)(sm + S_ROFF);
    float*    s_x   = sm + S_X;
    float*    s_ht  = sm + S_HT;
    float*    s_red = sm + S_RED;
    int*      s_ne  = (int*)(sm + S_NE);

    const int tid  = threadIdx.x;
    const int warp = tid >> 5;
    const int lane = tid & 31;
    const int b    = blockIdx.x;
    const int i0   = warp * 4;
    const int k0   = lane * 4;

    // ---- prologue: async-stage x, h, W_in ----
    {
        unsigned sx = (unsigned)__cvta_generic_to_shared(s_x);
        if (tid < 24) cp16(sx + tid * 16, g_x + b * 96 + tid * 4);
        unsigned sh = (unsigned)__cvta_generic_to_shared(s_ht);
        if (tid < 128) cp16(sh + tid * 16, g_h + b * 512 + tid * 4);
        stage_async(W_in, s_Wa, 512);
        CP_COMMIT();
        CP_WAIT0();
    }
    __syncthreads();

    // ---- d2 ----
    for (int p = tid; p < 1024; p += 256) {
        int i = p >> 5, j = p & 31;
        float dx = s_x[i * 3 + 0] - s_x[j * 3 + 0];
        float dy = s_x[i * 3 + 1] - s_x[j * 3 + 1];
        float dz = s_x[i * 3 + 2] - s_x[j * 3 + 2];
        s_d2[p] = dx * dx + dy * dy + dz * dz;
    }
    __syncthreads();

    // ---- adjacency masks + hg = h @ W_in + b_in (also prefetch We1[0] H0) ----
    #pragma unroll
    for (int rr = 0; rr < 4; rr++) {
        int i = i0 + rr;
        bool adj = (s_d2[i * 32 + lane] < 1.0f) && (lane != i);
        unsigned m = __ballot_sync(0xffffffffu, adj);
        if (lane == 0) s_rmask[i] = m;
    }
    stage_async(We1, s_Wb, 2048);   // We1[l=0] rows 0..63 (Wa slice of mi GEMM)
    CP_COMMIT();
    {
        float acc[4][4] = {};
        gemm_piece(s_ht, 16, 0, s_Wa, 16, i0, k0, acc);
        float4 bb = *(const float4*)&b_in[k0];
        #pragma unroll
        for (int rr = 0; rr < 4; rr++) {
            float4 o = { acc[rr][0] + bb.x, acc[rr][1] + bb.y,
                         acc[rr][2] + bb.z, acc[rr][3] + bb.w };
            *(float4*)&s_hg[(i0 + rr) * 128 + k0] = o;
        }
    }
    __syncthreads();

    // ---- edge-list scan (layer-invariant) ----
    if (warp == 0) {
        unsigned m = s_rmask[lane];
        int c = __popc(m);
        int inc = c;
        #pragma unroll
        for (int d = 1; d < 32; d <<= 1) {
            int n = __shfl_up_sync(0xffffffffu, inc, d);
            if (lane >= d) inc += n;
        }
        s_roff[lane] = inc - c;
        if (lane == 31) *s_ne = inc;
    }
    __syncthreads();
    #pragma unroll
    for (int rr = 0; rr < 4; rr++) {
        int i = i0 + rr;
        unsigned m = s_rmask[i];
        if ((m >> lane) & 1u) {
            int pos = s_roff[i] + __popc(m & ((1u << lane) - 1u));
            s_edge[pos] = (i << 5) | lane;
        }
    }
    CP_WAIT0();
    __syncthreads();
    const int nE = *s_ne;

    // ---- layers ----
    #pragma unroll 1
    for (int l = 0; l < 2; l++) {
        const float* We1l = We1 + l * (257 * 128);
        const float* We2l = We2 + l * 16384;
        const float* Wh1l = Wh1 + l * (256 * 128);
        const float* Wh2l = Wh2 + l * 16384;

        // mi = hg @ We1a + be1   (be1 folded here)
        {
            float acc[4][4] = {};
            float4 bb = *(const float4*)&be1[l * 128 + k0];
            phase128(s_hg, 128, We1l, We1l + 128 * 128, s_Wa, s_Wb, i0, k0, acc,
                [&](float a[4][4]) {
                    #pragma unroll
                    for (int rr = 0; rr < 4; rr++) {
                        float4 o = { a[rr][0] + bb.x, a[rr][1] + bb.y,
                                     a[rr][2] + bb.z, a[rr][3] + bb.w };
                        *(float4*)&s_mi[(i0 + rr) * 128 + k0] = o;
                    }
                });
        }
        // mj = hg @ We1b
        {
            float acc[4][4] = {};
            phase128(s_hg, 128, We1l + 128 * 128, We2l, s_Wa, s_Wb, i0, k0, acc,
                [&](float a[4][4]) {
                    #pragma unroll
                    for (int rr = 0; rr < 4; rr++) {
                        float4 o = { a[rr][0], a[rr][1], a[rr][2], a[rr][3] };
                        *(float4*)&s_mj[(i0 + rr) * 128 + k0] = o;
                    }
                });
        }

        // ---- pair phase: We2 rows 0..63 already in Wb; fetch rows 64..127 ----
        stage_async(We2l + 64 * 128, s_Wa, 2048);
        CP_COMMIT();
        for (int v = tid; v < 4096; v += 256) s_agg[v] = 0.0f;
        CP_WAIT0();
        __syncthreads();

        {
            const float4 wdv  = *(const float4*)&We1l[256 * 128 + k0];
            const float4 be2v = *(const float4*)&be2[l * 128 + k0];
            int buf = 0;
            for (int e0 = 0; e0 < nE; e0 += 32) {
                float* m1 = s_m1 + buf * 4096;
                #pragma unroll
                for (int rr = 0; rr < 4; rr++) {
                    int e = e0 + i0 + rr;
                    float4 v = { 0.f, 0.f, 0.f, 0.f };
                    if (e < nE) {
                        int ij = s_edge[e];
                        int i = ij >> 5, j = ij & 31;
                        float dd = s_d2[ij];
                        float4 miv = *(const float4*)&s_mi[i * 128 + k0];
                        float4 mjv = *(const float4*)&s_mj[j * 128 + k0];
                        v.x = silu_f(miv.x + mjv.x + dd * wdv.x);
                        v.y = silu_f(miv.y + mjv.y + dd * wdv.y);
                        v.z = silu_f(miv.z + mjv.z + dd * wdv.z);
                        v.w = silu_f(miv.w + mjv.w + dd * wdv.w);
                    }
                    *(float4*)&m1[(i0 + rr) * 128 + k0] = v;
                }
                __syncthreads();
                float y[4][4] = {};
                gemm_piece(m1, 128, 0,  s_Wb, 64, i0, k0, y);
                gemm_piece(m1, 128, 64, s_Wa, 64, i0, k0, y);
                #pragma unroll
                for (int rr = 0; rr < 4; rr++) {
                    int e = e0 + i0 + rr;
                    if (e < nE) {
                        int i = s_edge[e] >> 5;
                        float* ag = &s_agg[i * 128 + k0];
                        atomicAdd(ag + 0, silu_f(y[rr][0] + be2v.x));
                        atomicAdd(ag + 1, silu_f(y[rr][1] + be2v.y));
                        atomicAdd(ag + 2, silu_f(y[rr][2] + be2v.z));
                        atomicAdd(ag + 3, silu_f(y[rr][3] + be2v.w));
                    }
                }
                buf ^= 1;
            }
        }
        __syncthreads();
        // load Wh1a rows 0..63 (exposed, ~one L2 round-trip)
        stage_async(Wh1l, s_Wb, 2048);
        CP_COMMIT();
        CP_WAIT0();
        __syncthreads();

        // u = silu(hg @ Wh1a + agg @ Wh1b + bh1)  -> s_mi
        {
            float acc[4][4] = {};
            phase128(s_hg, 128, Wh1l, Wh1l + 128 * 128, s_Wa, s_Wb, i0, k0, acc,
                     [&](float a[4][4]) {});
            float4 bb = *(const float4*)&bh1[l * 128 + k0];
            phase128(s_agg, 128, Wh1l + 128 * 128, Wh2l, s_Wa, s_Wb, i0, k0, acc,
                [&](float a[4][4]) {
                    #pragma unroll
                    for (int rr = 0; rr < 4; rr++) {
                        float4 o = { silu_f(a[rr][0] + bb.x), silu_f(a[rr][1] + bb.y),
                                     silu_f(a[rr][2] + bb.z), silu_f(a[rr][3] + bb.w) };
                        *(float4*)&s_mi[(i0 + rr) * 128 + k0] = o;
                    }
                });
        }
        // hg += u @ Wh2 + bh2
        {
            const float* nxt = (l == 0) ? (We1 + 257 * 128) : W_out;
            float acc[4][4] = {};
            float4 bb = *(const float4*)&bh2[l * 128 + k0];
            phase128(s_mi, 128, Wh2l, nxt, s_Wa, s_Wb, i0, k0, acc,
                [&](float a[4][4]) {
                    #pragma unroll
                    for (int rr = 0; rr < 4; rr++) {
                        float4 cur = *(float4*)&s_hg[(i0 + rr) * 128 + k0];
                        cur.x += a[rr][0] + bb.x;
                        cur.y += a[rr][1] + bb.y;
                        cur.z += a[rr][2] + bb.z;
                        cur.w += a[rr][3] + bb.w;
                        *(float4*)&s_hg[(i0 + rr) * 128 + k0] = cur;
                    }
                });
        }
    }

    // ---- head: ho = hg @ W_out + b_out -> s_mj ----
    {
        float acc[4][4] = {};
        float4 bb = *(const float4*)&b_out[k0];
        phase128(s_hg, 128, W_out, Wn1, s_Wa, s_Wb, i0, k0, acc,
            [&](float a[4][4]) {
                #pragma unroll
                for (int rr = 0; rr < 4; rr++) {
                    float4 o = { a[rr][0] + bb.x, a[rr][1] + bb.y,
                                 a[rr][2] + bb.z, a[rr][3] + bb.w };
                    *(float4*)&s_mj[(i0 + rr) * 128 + k0] = o;
                }
            });
    }
    // t1 = silu(ho @ Wn1 + bn1) -> s_mi
    {
        float acc[4][4] = {};
        float4 bb = *(const float4*)&bn1[k0];
        phase128(s_mj, 128, Wn1, (const float*)0, s_Wa, s_Wb, i0, k0, acc,
            [&](float a[4][4]) {
                #pragma unroll
                for (int rr = 0; rr < 4; rr++) {
                    float4 o = { silu_f(a[rr][0] + bb.x), silu_f(a[rr][1] + bb.y),
                                 silu_f(a[rr][2] + bb.z), silu_f(a[rr][3] + bb.w) };
                    *(float4*)&s_mi[(i0 + rr) * 128 + k0] = o;
                }
            });
    }

    // ---- out[b] = (colsum t1) . Wn2 + 32*bn2 ----
    float part = 0.0f;
    if (tid < 128) {
        float s = 0.0f;
        #pragma unroll
        for (int i = 0; i < 32; i++) s += s_mi[i * 128 + tid];
        part = s * Wn2[tid];
    }
    #pragma unroll
    for (int off = 16; off > 0; off >>= 1)
        part += __shfl_down_sync(0xffffffffu, part, off);
    if (warp < 4 && lane == 0) s_red[warp] = part;
    __syncthreads();
    if (tid == 0)
        g_out[b] = s_red[0] + s_red[1] + s_red[2] + s_red[3] + 32.0f * bn2[0];
}

extern "C" void kernel_launch(void* const* d_in, const int* in_sizes, int n_in,
                              void* d_out, int out_size) {
    const float* g_h   = (const float*)d_in[0];
    const float* g_x   = (const float*)d_in[1];
    const float* W_in  = (const float*)d_in[3];
    const float* b_in  = (const float*)d_in[4];
    const float* We1   = (const float*)d_in[5];
    const float* be1   = (const float*)d_in[6];
    const float* We2   = (const float*)d_in[7];
    const float* be2   = (const float*)d_in[8];
    const float* Wh1   = (const float*)d_in[9];
    const float* bh1   = (const float*)d_in[10];
    const float* Wh2   = (const float*)d_in[11];
    const float* bh2   = (const float*)d_in[12];
    const float* W_out = (const float*)d_in[13];
    const float* b_out = (const float*)d_in[14];
    const float* Wn1   = (const float*)d_in[15];
    const float* bn1   = (const float*)d_in[16];
    const float* Wn2   = (const float*)d_in[17];
    const float* bn2   = (const float*)d_in[18];
    float* out = (float*)d_out;

    const int smem_bytes = SM_FLOATS * 4;
    cudaFuncSetAttribute(sake_kernel, cudaFuncAttributeMaxDynamicSharedMemorySize,
                         smem_bytes);
    sake_kernel<<<NB, 256, smem_bytes>>>(
        g_h, g_x, W_in, b_in, We1, be1, We2, be2, Wh1, bh1, Wh2, bh2,
        W_out, b_out, Wn1, bn1, Wn2, bn2, out);
}

// round 3
// speedup vs baseline: 1.1589x; 1.1589x over previous
#include <cuda_runtime.h>

// SAKE GNN fully fused, one CTA per graph (B=512, M=32, H=128, L=2).
// R3: packed fp32 (fma.rn.f32x2 -> FFMA2) in all GEMMs + balanced per-warp
//     edge slices with register aggregation (atomics only on i-change).

#define NB 512
typedef unsigned long long u64;

// ---- shared memory layout (float offsets) ----
#define S_HG    0        // 32x128
#define S_MI    4096
#define S_MJ    8192
#define S_AGG   12288
#define S_W     16384    // 128x128 weight staging
#define S_M1    32768    // 8 warps x 4 rows x 128
#define S_D2    36864    // 32x32
#define S_EDGE  37888    // 1024 ints
#define S_RMASK 38912
#define S_ROFF  38944
#define S_X     38976    // 96
#define S_HT    39072    // 32x16
#define S_RED   39584
#define S_NE    39592
#define SM_FLOATS 39600

__device__ __forceinline__ float silu_f(float v) {
    return __fdividef(v, 1.0f + __expf(-v));
}
__device__ __forceinline__ u64 pk2(float x) {
    u64 r; asm("mov.b64 %0, {%1, %1};" : "=l"(r) : "f"(x)); return r;
}
__device__ __forceinline__ void ffma2(u64& d, u64 a, u64 b) {
    asm("fma.rn.f32x2 %0, %1, %2, %0;" : "+l"(d) : "l"(a), "l"(b));
}
__device__ __forceinline__ float2 unpk(u64 v) {
    float2 f; asm("mov.b64 {%0, %1}, %2;" : "=f"(f.x), "=f"(f.y) : "l"(v)); return f;
}
// acc pair -> float4 covering cols k0..k0+3
__device__ __forceinline__ float4 acc4(u64 p0, u64 p1) {
    float2 a = unpk(p0), b = unpk(p1);
    float4 r = { a.x, a.y, b.x, b.y };
    return r;
}

__device__ __forceinline__ void cp16(unsigned saddr, const float* g) {
    asm volatile("cp.async.cg.shared.global [%0], [%1], 16;" :: "r"(saddr), "l"(g));
}
#define CP_COMMIT() asm volatile("cp.async.commit_group;")
#define CP_WAIT0()  asm volatile("cp.async.wait_group 0;" ::: "memory")

__device__ __forceinline__ void stage_async(const float* __restrict__ g,
                                            float* s, int nf4) {
    unsigned sa = (unsigned)__cvta_generic_to_shared(s);
    for (int v = threadIdx.x; v < nf4; v += 256)
        cp16(sa + v * 16, g + v * 4);
}

// acc[rr][p] (f32x2) += sum_h X[(i0+rr)*ldx+h] * W[h*128 + k0 + 2p + {0,1}]
__device__ __forceinline__ void gemm2(const float* __restrict__ sX, int ldx,
                                      const float* __restrict__ sW, int nh,
                                      int i0, int k0, u64 acc[4][2]) {
    #pragma unroll 1
    for (int h = 0; h < nh; h += 4) {
        ulonglong2 w0 = *(const ulonglong2*)&sW[(h + 0) * 128 + k0];
        ulonglong2 w1 = *(const ulonglong2*)&sW[(h + 1) * 128 + k0];
        ulonglong2 w2 = *(const ulonglong2*)&sW[(h + 2) * 128 + k0];
        ulonglong2 w3 = *(const ulonglong2*)&sW[(h + 3) * 128 + k0];
        #pragma unroll
        for (int rr = 0; rr < 4; rr++) {
            float4 a = *(const float4*)&sX[(i0 + rr) * ldx + h];
            u64 a0 = pk2(a.x), a1 = pk2(a.y), a2 = pk2(a.z), a3 = pk2(a.w);
            ffma2(acc[rr][0], a0, w0.x); ffma2(acc[rr][1], a0, w0.y);
            ffma2(acc[rr][0], a1, w1.x); ffma2(acc[rr][1], a1, w1.y);
            ffma2(acc[rr][0], a2, w2.x); ffma2(acc[rr][1], a2, w2.y);
            ffma2(acc[rr][0], a3, w3.x); ffma2(acc[rr][1], a3, w3.y);
        }
    }
}

__global__ void __launch_bounds__(256, 1)
sake_kernel(const float* __restrict__ g_h, const float* __restrict__ g_x,
            const float* __restrict__ W_in, const float* __restrict__ b_in,
            const float* __restrict__ We1, const float* __restrict__ be1,
            const float* __restrict__ We2, const float* __restrict__ be2,
            const float* __restrict__ Wh1, const float* __restrict__ bh1,
            const float* __restrict__ Wh2, const float* __restrict__ bh2,
            const float* __restrict__ W_out, const float* __restrict__ b_out,
            const float* __restrict__ Wn1, const float* __restrict__ bn1,
            const float* __restrict__ Wn2, const float* __restrict__ bn2,
            float* __restrict__ g_out)
{
    extern __shared__ float sm[];
    float*    s_hg  = sm + S_HG;
    float*    s_mi  = sm + S_MI;
    float*    s_mj  = sm + S_MJ;
    float*    s_agg = sm + S_AGG;
    float*    s_W   = sm + S_W;
    float*    s_m1  = sm + S_M1;
    float*    s_d2  = sm + S_D2;
    int*      s_edge  = (int*)(sm + S_EDGE);
    unsigned* s_rmask = (unsigned*)(sm + S_RMASK);
    int*      s_roff  = (int*)(sm + S_ROFF);
    float*    s_x   = sm + S_X;
    float*    s_ht  = sm + S_HT;
    float*    s_red = sm + S_RED;
    int*      s_ne  = (int*)(sm + S_NE);

    const int tid  = threadIdx.x;
    const int warp = tid >> 5;
    const int lane = tid & 31;
    const int b    = blockIdx.x;
    const int i0   = warp * 4;
    const int k0   = lane * 4;

    // ---- prologue: stage x, h, W_in ----
    {
        unsigned sx = (unsigned)__cvta_generic_to_shared(s_x);
        if (tid < 24) cp16(sx + tid * 16, g_x + b * 96 + tid * 4);
        unsigned sh = (unsigned)__cvta_generic_to_shared(s_ht);
        if (tid < 128) cp16(sh + tid * 16, g_h + b * 512 + tid * 4);
        stage_async(W_in, s_W, 512);
        CP_COMMIT(); CP_WAIT0();
    }
    __syncthreads();

    // ---- d2 ----
    for (int p = tid; p < 1024; p += 256) {
        int i = p >> 5, j = p & 31;
        float dx = s_x[i * 3 + 0] - s_x[j * 3 + 0];
        float dy = s_x[i * 3 + 1] - s_x[j * 3 + 1];
        float dz = s_x[i * 3 + 2] - s_x[j * 3 + 2];
        s_d2[p] = dx * dx + dy * dy + dz * dz;
    }
    __syncthreads();

    // ---- adjacency masks + hg = h @ W_in + b_in ----
    #pragma unroll
    for (int rr = 0; rr < 4; rr++) {
        int i = i0 + rr;
        bool adj = (s_d2[i * 32 + lane] < 1.0f) && (lane != i);
        unsigned m = __ballot_sync(0xffffffffu, adj);
        if (lane == 0) s_rmask[i] = m;
    }
    {
        u64 acc[4][2] = {};
        gemm2(s_ht, 16, s_W, 16, i0, k0, acc);
        float4 bb = *(const float4*)&b_in[k0];
        #pragma unroll
        for (int rr = 0; rr < 4; rr++) {
            float4 o = acc4(acc[rr][0], acc[rr][1]);
            o.x += bb.x; o.y += bb.y; o.z += bb.z; o.w += bb.w;
            *(float4*)&s_hg[(i0 + rr) * 128 + k0] = o;
        }
    }
    __syncthreads();

    // ---- edge-list scan (layer-invariant, sorted by i) ----
    if (warp == 0) {
        unsigned m = s_rmask[lane];
        int c = __popc(m);
        int inc = c;
        #pragma unroll
        for (int d = 1; d < 32; d <<= 1) {
            int n = __shfl_up_sync(0xffffffffu, inc, d);
            if (lane >= d) inc += n;
        }
        s_roff[lane] = inc - c;
        if (lane == 31) *s_ne = inc;
    }
    __syncthreads();
    #pragma unroll
    for (int rr = 0; rr < 4; rr++) {
        int i = i0 + rr;
        unsigned m = s_rmask[i];
        if ((m >> lane) & 1u) {
            int pos = s_roff[i] + __popc(m & ((1u << lane) - 1u));
            s_edge[pos] = (i << 5) | lane;
        }
    }
    __syncthreads();
    const int nE = *s_ne;
    const int nper = (nE + 7) >> 3;

    // ---- layers ----
    #pragma unroll 1
    for (int l = 0; l < 2; l++) {
        const float* We1l = We1 + l * (257 * 128);
        const float* We2l = We2 + l * 16384;
        const float* Wh1l = Wh1 + l * (256 * 128);
        const float* Wh2l = Wh2 + l * 16384;

        // mi = hg @ We1a + be1
        stage_async(We1l, s_W, 4096); CP_COMMIT(); CP_WAIT0();
        __syncthreads();
        {
            u64 acc[4][2] = {};
            gemm2(s_hg, 128, s_W, 128, i0, k0, acc);
            float4 bb = *(const float4*)&be1[l * 128 + k0];
            #pragma unroll
            for (int rr = 0; rr < 4; rr++) {
                float4 o = acc4(acc[rr][0], acc[rr][1]);
                o.x += bb.x; o.y += bb.y; o.z += bb.z; o.w += bb.w;
                *(float4*)&s_mi[(i0 + rr) * 128 + k0] = o;
            }
        }
        __syncthreads();

        // mj = hg @ We1b
        stage_async(We1l + 16384, s_W, 4096); CP_COMMIT(); CP_WAIT0();
        __syncthreads();
        {
            u64 acc[4][2] = {};
            gemm2(s_hg, 128, s_W, 128, i0, k0, acc);
            #pragma unroll
            for (int rr = 0; rr < 4; rr++)
                *(float4*)&s_mj[(i0 + rr) * 128 + k0] = acc4(acc[rr][0], acc[rr][1]);
        }
        __syncthreads();

        // stage We2; zero agg
        stage_async(We2l, s_W, 4096); CP_COMMIT();
        for (int v = tid; v < 4096; v += 256) s_agg[v] = 0.0f;
        CP_WAIT0();
        __syncthreads();

        // ---- balanced pair phase: each warp owns a contiguous edge slice ----
        {
            const float4 wdv  = *(const float4*)&We1l[256 * 128 + k0];
            const float4 be2v = *(const float4*)&be2[l * 128 + k0];
            float* m1 = s_m1 + warp * 512;
            const int e_lo = min(warp * nper, nE);
            const int e_hi = min(e_lo + nper, nE);

            int   cur_i = -1;
            float a0 = 0.f, a1 = 0.f, a2 = 0.f, a3 = 0.f;

            for (int e0 = e_lo; e0 < e_hi; e0 += 4) {
                // build up to 4 rows of m1 = silu(mi[i] + mj[j] + d2*wd + be1)
                #pragma unroll
                for (int rr = 0; rr < 4; rr++) {
                    int e = e0 + rr;
                    int ij = s_edge[e < e_hi ? e : (e_hi - 1)];
                    int i = ij >> 5, j = ij & 31;
                    float dd = s_d2[ij];
                    float4 miv = *(const float4*)&s_mi[i * 128 + k0];
                    float4 mjv = *(const float4*)&s_mj[j * 128 + k0];
                    float4 v;
                    v.x = silu_f(miv.x + mjv.x + dd * wdv.x);
                    v.y = silu_f(miv.y + mjv.y + dd * wdv.y);
                    v.z = silu_f(miv.z + mjv.z + dd * wdv.z);
                    v.w = silu_f(miv.w + mjv.w + dd * wdv.w);
                    *(float4*)&m1[rr * 128 + k0] = v;
                }
                __syncwarp();
                u64 y[4][2] = {};
                gemm2(m1, 128, s_W, 128, 0, k0, y);
                __syncwarp();   // protect m1 before next chunk overwrites

                #pragma unroll
                for (int rr = 0; rr < 4; rr++) {
                    int e = e0 + rr;
                    if (e < e_hi) {
                        int i = s_edge[e] >> 5;   // uniform across warp
                        float4 o = acc4(y[rr][0], y[rr][1]);
                        float v0 = silu_f(o.x + be2v.x);
                        float v1 = silu_f(o.y + be2v.y);
                        float v2 = silu_f(o.z + be2v.z);
                        float v3 = silu_f(o.w + be2v.w);
                        if (i != cur_i) {
                            if (cur_i >= 0) {
                                float* ag = &s_agg[cur_i * 128 + k0];
                                atomicAdd(ag + 0, a0); atomicAdd(ag + 1, a1);
                                atomicAdd(ag + 2, a2); atomicAdd(ag + 3, a3);
                            }
                            cur_i = i;
                            a0 = v0; a1 = v1; a2 = v2; a3 = v3;
                        } else {
                            a0 += v0; a1 += v1; a2 += v2; a3 += v3;
                        }
                    }
                }
            }
            if (cur_i >= 0) {
                float* ag = &s_agg[cur_i * 128 + k0];
                atomicAdd(ag + 0, a0); atomicAdd(ag + 1, a1);
                atomicAdd(ag + 2, a2); atomicAdd(ag + 3, a3);
            }
        }
        __syncthreads();

        // u = silu(hg @ Wh1a + agg @ Wh1b + bh1) -> s_mi
        stage_async(Wh1l, s_W, 4096); CP_COMMIT(); CP_WAIT0();
        __syncthreads();
        u64 acc[4][2] = {};
        gemm2(s_hg, 128, s_W, 128, i0, k0, acc);
        __syncthreads();
        stage_async(Wh1l + 16384, s_W, 4096); CP_COMMIT(); CP_WAIT0();
        __syncthreads();
        gemm2(s_agg, 128, s_W, 128, i0, k0, acc);
        {
            float4 bb = *(const float4*)&bh1[l * 128 + k0];
            #pragma unroll
            for (int rr = 0; rr < 4; rr++) {
                float4 o = acc4(acc[rr][0], acc[rr][1]);
                float4 u4 = { silu_f(o.x + bb.x), silu_f(o.y + bb.y),
                              silu_f(o.z + bb.z), silu_f(o.w + bb.w) };
                *(float4*)&s_mi[(i0 + rr) * 128 + k0] = u4;
            }
        }
        __syncthreads();

        // hg += u @ Wh2 + bh2
        stage_async(Wh2l, s_W, 4096); CP_COMMIT(); CP_WAIT0();
        __syncthreads();
        {
            u64 acc2[4][2] = {};
            gemm2(s_mi, 128, s_W, 128, i0, k0, acc2);
            float4 bb = *(const float4*)&bh2[l * 128 + k0];
            #pragma unroll
            for (int rr = 0; rr < 4; rr++) {
                float4 o = acc4(acc2[rr][0], acc2[rr][1]);
                float4 cur = *(float4*)&s_hg[(i0 + rr) * 128 + k0];
                cur.x += o.x + bb.x; cur.y += o.y + bb.y;
                cur.z += o.z + bb.z; cur.w += o.w + bb.w;
                *(float4*)&s_hg[(i0 + rr) * 128 + k0] = cur;
            }
        }
        __syncthreads();
    }

    // ---- head: ho = hg @ W_out + b_out -> s_mj ----
    stage_async(W_out, s_W, 4096); CP_COMMIT(); CP_WAIT0();
    __syncthreads();
    {
        u64 acc[4][2] = {};
        gemm2(s_hg, 128, s_W, 128, i0, k0, acc);
        float4 bb = *(const float4*)&b_out[k0];
        #pragma unroll
        for (int rr = 0; rr < 4; rr++) {
            float4 o = acc4(acc[rr][0], acc[rr][1]);
            o.x += bb.x; o.y += bb.y; o.z += bb.z; o.w += bb.w;
            *(float4*)&s_mj[(i0 + rr) * 128 + k0] = o;
        }
    }
    __syncthreads();

    // t1 = silu(ho @ Wn1 + bn1) -> s_mi
    stage_async(Wn1, s_W, 4096); CP_COMMIT(); CP_WAIT0();
    __syncthreads();
    {
        u64 acc[4][2] = {};
        gemm2(s_mj, 128, s_W, 128, i0, k0, acc);
        float4 bb = *(const float4*)&bn1[k0];
        #pragma unroll
        for (int rr = 0; rr < 4; rr++) {
            float4 o = acc4(acc[rr][0], acc[rr][1]);
            float4 t = { silu_f(o.x + bb.x), silu_f(o.y + bb.y),
                         silu_f(o.z + bb.z), silu_f(o.w + bb.w) };
            *(float4*)&s_mi[(i0 + rr) * 128 + k0] = t;
        }
    }
    __syncthreads();

    // ---- out[b] = (colsum t1) . Wn2 + 32*bn2 ----
    float part = 0.0f;
    if (tid < 128) {
        float s = 0.0f;
        #pragma unroll
        for (int i = 0; i < 32; i++) s += s_mi[i * 128 + tid];
        part = s * Wn2[tid];
    }
    #pragma unroll
    for (int off = 16; off > 0; off >>= 1)
        part += __shfl_down_sync(0xffffffffu, part, off);
    if (warp < 4 && lane == 0) s_red[warp] = part;
    __syncthreads();
    if (tid == 0)
        g_out[b] = s_red[0] + s_red[1] + s_red[2] + s_red[3] + 32.0f * bn2[0];
}

extern "C" void kernel_launch(void* const* d_in, const int* in_sizes, int n_in,
                              void* d_out, int out_size) {
    const float* g_h   = (const float*)d_in[0];
    const float* g_x   = (const float*)d_in[1];
    const float* W_in  = (const float*)d_in[3];
    const float* b_in  = (const float*)d_in[4];
    const float* We1   = (const float*)d_in[5];
    const float* be1   = (const float*)d_in[6];
    const float* We2   = (const float*)d_in[7];
    const float* be2   = (const float*)d_in[8];
    const float* Wh1   = (const float*)d_in[9];
    const float* bh1   = (const float*)d_in[10];
    const float* Wh2   = (const float*)d_in[11];
    const float* bh2   = (const float*)d_in[12];
    const float* W_out = (const float*)d_in[13];
    const float* b_out = (const float*)d_in[14];
    const float* Wn1   = (const float*)d_in[15];
    const float* bn1   = (const float*)d_in[16];
    const float* Wn2   = (const float*)d_in[17];
    const float* bn2   = (const float*)d_in[18];
    float* out = (float*)d_out;

    const int smem_bytes = SM_FLOATS * 4;
    cudaFuncSetAttribute(sake_kernel, cudaFuncAttributeMaxDynamicSharedMemorySize,
                         smem_bytes);
    sake_kernel<<<NB, 256, smem_bytes>>>(
        g_h, g_x, W_in, b_in, We1, be1, We2, be2, Wh1, bh1, Wh2, bh2,
        W_out, b_out, Wn1, bn1, Wn2, bn2, out);
}